// round 15
// baseline (speedup 1.0000x reference)
#include <cuda_runtime.h>
#include <cuda_fp16.h>
#include <math.h>

#define SEQ 4096
#define NH 8
#define HD 32
#define DM 256
#define IN_F 256
#define MW (SEQ / 32)  // mask words per row

typedef unsigned int u32;

// ---------------- scratch (static device globals; no allocation) ----------------
__device__ __align__(16) __half g_Qh[NH * SEQ * HD];  // fp16 hi, Q pre-scaled by log2e/sqrt(32)
__device__ __align__(16) __half g_Ql[NH * SEQ * HD];  // fp16 residual
__device__ __align__(16) __half g_Kh[NH * SEQ * HD];
__device__ __align__(16) __half g_Kl[NH * SEQ * HD];
__device__ __align__(16) __half g_Vh[NH * SEQ * HD];
__device__ __align__(16) __half g_Vl[NH * SEQ * HD];
__device__ float g_inv[NH * SEQ];              // 1 / softmax rowsum
__device__ float g_ctx[SEQ * DM];              // normalized context
__device__ float g_fc[SEQ * DM];
__device__ u32 g_mbits[(size_t)SEQ * MW];      // bit-packed mask (bit=1 => masked), 2MB
__device__ int g_mask_mode;

// ---------------- small helpers ----------------
__device__ __forceinline__ u32 s2u(const void* p) { return (u32)__cvta_generic_to_shared(p); }

__device__ __forceinline__ void cp16(u32 dst, const void* src) {
    asm volatile("cp.async.cg.shared.global [%0], [%1], 16;" :: "r"(dst), "l"(src));
}
__device__ __forceinline__ void cp_commit() { asm volatile("cp.async.commit_group;"); }
template <int N>
__device__ __forceinline__ void cp_wait() { asm volatile("cp.async.wait_group %0;" :: "n"(N)); }

__device__ __forceinline__ void ldsm_x4(u32& r0, u32& r1, u32& r2, u32& r3, u32 addr) {
    asm volatile("ldmatrix.sync.aligned.m8n8.x4.shared.b16 {%0,%1,%2,%3}, [%4];"
                 : "=r"(r0), "=r"(r1), "=r"(r2), "=r"(r3) : "r"(addr));
}
__device__ __forceinline__ void ldsm_x4t(u32& r0, u32& r1, u32& r2, u32& r3, u32 addr) {
    asm volatile("ldmatrix.sync.aligned.m8n8.x4.trans.shared.b16 {%0,%1,%2,%3}, [%4];"
                 : "=r"(r0), "=r"(r1), "=r"(r2), "=r"(r3) : "r"(addr));
}
__device__ __forceinline__ void mma_f16(float* c, const u32* a, u32 b0, u32 b1) {
    asm volatile(
        "mma.sync.aligned.m16n8k16.row.col.f32.f16.f16.f32 "
        "{%0,%1,%2,%3}, {%4,%5,%6,%7}, {%8,%9}, {%0,%1,%2,%3};"
        : "+f"(c[0]), "+f"(c[1]), "+f"(c[2]), "+f"(c[3])
        : "r"(a[0]), "r"(a[1]), "r"(a[2]), "r"(a[3]), "r"(b0), "r"(b1));
}
__device__ __forceinline__ u32 hpack(float lo, float hi) {
    u32 r;
    asm("cvt.rn.f16x2.f32 %0, %1, %2;" : "=r"(r) : "f"(hi), "f"(lo));
    return r;
}
// scores are pre-scaled by log2e: exp(s) == ex2(c), single MUFU op
__device__ __forceinline__ float ex2(float x) {
    float r;
    asm("ex2.approx.f32 %0, %1;" : "=f"(r) : "f"(x));
    return r;
}

// ---------------- mask dtype detection + bit-pack canonicalization ----------------
__global__ void detect_mask_kernel(const void* m) {
    const unsigned int* p = (const unsigned int*)m;
    int lane = threadIdx.x;
    int isint = 1, isfloat = 1;
    for (int i = lane; i < 256; i += 32) {
        unsigned int v = p[i];
        if (v > 1u) isint = 0;
        if (v != 0u && v != 0x3F800000u) isfloat = 0;
    }
    isint = __all_sync(0xFFFFFFFFu, isint);
    isfloat = __all_sync(0xFFFFFFFFu, isfloat);
    if (lane == 0) g_mask_mode = isint ? 1 : (isfloat ? 2 : 0);
}

__global__ void conv_mask_kernel(const void* m) {
    int mode = g_mask_mode;
    int lane = threadIdx.x & 31;
    size_t idx = (size_t)blockIdx.x * blockDim.x + threadIdx.x;
    size_t stride = (size_t)gridDim.x * blockDim.x;
    size_t total = (size_t)SEQ * SEQ;
    for (size_t i = idx; i < total; i += stride) {
        int pred;
        if (mode == 1)      pred = (((const int*)m)[i] != 0);
        else if (mode == 2) pred = (((const float*)m)[i] != 0.0f);
        else                pred = (((const unsigned char*)m)[i] != 0);
        u32 b = __ballot_sync(0xFFFFFFFFu, pred);
        if (lane == 0) g_mbits[i >> 5] = b;
    }
}

// ---------------- input projections: Y = X @ W^T -> fp16 hi/lo, split heads ----------------
__global__ __launch_bounds__(256) void proj_kernel(const float* __restrict__ XQ,
                                                   const float* __restrict__ XK,
                                                   const float* __restrict__ XV,
                                                   const float* __restrict__ WQ,
                                                   const float* __restrict__ WK,
                                                   const float* __restrict__ WV) {
    int which = blockIdx.z;
    const float* X = (which == 0) ? XQ : (which == 1) ? XK : XV;
    const float* W = (which == 0) ? WQ : (which == 1) ? WK : WV;
    __half* oh = (which == 0) ? g_Qh : (which == 1) ? g_Kh : g_Vh;
    __half* ol = (which == 0) ? g_Ql : (which == 1) ? g_Kl : g_Vl;
    // Q carries 1/sqrt(32) * log2(e) so softmax exp becomes a bare ex2
    float scale = (which == 0) ? (0.17677669529663687f * 1.4426950408889634f) : 1.0f;
    __shared__ float Xs[16][68];
    __shared__ float Ws[16][68];
    int bm = blockIdx.y * 64, bn = blockIdx.x * 64;
    int tid = threadIdx.x;
    int tx = (tid & 15) * 4, ty = (tid >> 4) * 4;
    float acc[4][4] = {};
    for (int k0 = 0; k0 < IN_F; k0 += 16) {
        for (int i = tid; i < 1024; i += 256) {
            int r = i >> 4, kk = i & 15;
            Xs[kk][r] = X[(size_t)(bm + r) * IN_F + k0 + kk];
            Ws[kk][r] = W[(size_t)(bn + r) * IN_F + k0 + kk];
        }
        __syncthreads();
#pragma unroll
        for (int kk = 0; kk < 16; kk++) {
            float xv[4], wv[4];
#pragma unroll
            for (int i = 0; i < 4; i++) xv[i] = Xs[kk][ty + i];
#pragma unroll
            for (int j = 0; j < 4; j++) wv[j] = Ws[kk][tx + j];
#pragma unroll
            for (int i = 0; i < 4; i++)
#pragma unroll
                for (int j = 0; j < 4; j++) acc[i][j] += xv[i] * wv[j];
        }
        __syncthreads();
    }
#pragma unroll
    for (int i = 0; i < 4; i++) {
        int m = bm + ty + i;
#pragma unroll
        for (int j = 0; j < 4; j++) {
            int o = bn + tx + j;
            float v = acc[i][j] * scale;
            __half hi = __float2half_rn(v);
            float lo = v - __half2float(hi);
            size_t dst = (size_t)(o >> 5) * (SEQ * HD) + (size_t)m * HD + (o & 31);
            oh[dst] = hi;
            ol[dst] = __float2half_rn(lo);
        }
    }
}

#define QSTR 40  // half row stride for Q/K/V smem tiles (80B: 16B-aligned, ldsm conflict-free)

// ================= rowsum kernel: g_inv = 1/sum(exp(scores)) =================
// q-tile 32 (grid 1024). Warp (qg = w&1, kg = w>>1) owns
// q rows [qg*16,+16) x keys [kg*16,+16) of each 64-key tile. hi-only fp16 scores.
__global__ __launch_bounds__(256, 5) void rowsum_kernel() {
    __shared__ __align__(16) __half sQ[32 * QSTR];
    __shared__ __align__(16) __half sK[3][64 * QSTR];
    __shared__ float sred[32][5];

    int h = blockIdx.y;
    int qb = blockIdx.x * 32;
    int tid = threadIdx.x, w = tid >> 5, lane = tid & 31;
    int g = lane >> 2, tig = lane & 3;
    int qg = w & 1, kg = w >> 1;

    // stage Q hi (32 rows x 4 chunks)
    if (tid < 128) {
        int r = tid >> 2, c = tid & 3;
        *(uint4*)(sQ + r * QSTR + c * 8) =
            *(const uint4*)(g_Qh + ((size_t)h * SEQ + qb + r) * HD + c * 8);
    }
    __syncthreads();

    // A-fragments: 1 row group of 16 (hi only) = 8 regs
    u32 qa[2][4];
    {
        int colb = ((lane >> 4) & 1) * 8;
        int row = qg * 16 + (lane & 15);
#pragma unroll
        for (int kc = 0; kc < 2; kc++)
            ldsm_x4(qa[kc][0], qa[kc][1], qa[kc][2], qa[kc][3],
                    s2u(&sQ[row * QSTR + kc * 16 + colb]));
    }

    const __half* Khp = g_Kh + (size_t)h * SEQ * HD;
    int ldr = tid >> 2, ldc = tid & 3;
    float rs0 = 0.0f, rs1 = 0.0f;

    int q0 = qb + qg * 16 + g;
    const u32* mwp0 = g_mbits + (size_t)q0 * MW + (kg >> 1);
    const u32* mwp1 = mwp0 + (size_t)8 * MW;
    int bitbase = (kg & 1) * 16 + tig * 2;

#define RS_ISSUE(stage, kc0)                                                       \
    {                                                                              \
        cp16(s2u(sK[(stage)] + ldr * QSTR + ldc * 8),                              \
             Khp + (size_t)((kc0) + ldr) * HD + ldc * 8);                          \
        cp_commit();                                                               \
    }

    RS_ISSUE(0, 0);
    RS_ISSUE(1, 64);
    for (int t = 0; t < 64; t++) {
        if (t < 63) cp_wait<1>(); else cp_wait<0>();
        __syncthreads();
        if (t + 2 < 64) RS_ISSUE((t + 2) % 3, (t + 2) * 64);
        const __half* sKb = sK[t % 3];
        u32 m0 = mwp0[t * 2] >> bitbase;
        u32 m1 = mwp1[t * 2] >> bitbase;
#pragma unroll
        for (int j = 0; j < 2; j++) {
            u32 bh[4];
            ldsm_x4(bh[0], bh[1], bh[2], bh[3],
                    s2u(sKb + (kg * 16 + j * 8 + (lane & 7)) * QSTR + ((lane >> 3) & 3) * 8));
            float c[4] = {0, 0, 0, 0};
            mma_f16(c, qa[0], bh[0], bh[1]);
            mma_f16(c, qa[1], bh[2], bh[3]);
            u32 b0 = m0 >> (j * 8), b1 = m1 >> (j * 8);
            rs0 += ((b0 & 1) ? 0.0f : ex2(c[0])) + ((b0 & 2) ? 0.0f : ex2(c[1]));
            rs1 += ((b1 & 1) ? 0.0f : ex2(c[2])) + ((b1 & 2) ? 0.0f : ex2(c[3]));
        }
    }
#undef RS_ISSUE

    rs0 += __shfl_xor_sync(0xFFFFFFFFu, rs0, 1);
    rs0 += __shfl_xor_sync(0xFFFFFFFFu, rs0, 2);
    rs1 += __shfl_xor_sync(0xFFFFFFFFu, rs1, 1);
    rs1 += __shfl_xor_sync(0xFFFFFFFFu, rs1, 2);
    if (tig == 0) {
        int r = qg * 16 + g;
        sred[r][kg] = rs0;
        sred[r + 8][kg] = rs1;
    }
    __syncthreads();
    if (tid < 32)
        g_inv[h * SEQ + qb + tid] =
            1.0f / (sred[tid][0] + sred[tid][1] + sred[tid][2] + sred[tid][3]);
}

// ================= attention kernel: normalized attn + context (single pass) =================
// q-tile 64 (grid 512, 3 CTAs/SM) for occupancy/latency hiding.
// Warp (qg = w&3, kg = w>>2): 16 q rows x 32 keys per 64-key tile.
// 2-stage KV pipeline, per-tile Es fp32 smem staging + coalesced float4 row copy.
#define ESTR 72                                              // Es float row stride
#define KVBYTES (4 * 64 * QSTR * 2)                          // 20480 per stage
#define ATTN_SMEM (2 * 64 * QSTR * 2 + 2 * KVBYTES + 64 * ESTR * 4)  // 69632

__global__ __launch_bounds__(256, 3) void attn_kernel(float* __restrict__ attn_out) {
    extern __shared__ char smem_raw[];
    __half* sQh = (__half*)smem_raw;
    __half* sQl = sQh + 64 * QSTR;
    char* sKV0 = smem_raw + 2 * 64 * QSTR * 2;
    float* sEs = (float*)(sKV0 + 2 * KVBYTES);

    int h = blockIdx.y;
    int qb = blockIdx.x * 64;
    int tid = threadIdx.x, w = tid >> 5, lane = tid & 31;
    int g = lane >> 2, tig = lane & 3;
    int qg = w & 3, kg = w >> 2;

    // stage Q hi/lo (64 rows x 4 chunks, 1 uint4/thread each)
    {
        int r = tid >> 2, c = tid & 3;
        *(uint4*)(sQh + r * QSTR + c * 8) =
            *(const uint4*)(g_Qh + ((size_t)h * SEQ + qb + r) * HD + c * 8);
        *(uint4*)(sQl + r * QSTR + c * 8) =
            *(const uint4*)(g_Ql + ((size_t)h * SEQ + qb + r) * HD + c * 8);
    }
    __syncthreads();

    // A-fragments: one 16-row group, hi+lo = 16 regs
    u32 qa_h[2][4], qa_l[2][4];
    {
        int colb = ((lane >> 4) & 1) * 8;
        int row = qg * 16 + (lane & 15);
#pragma unroll
        for (int kc = 0; kc < 2; kc++) {
            ldsm_x4(qa_h[kc][0], qa_h[kc][1], qa_h[kc][2], qa_h[kc][3],
                    s2u(&sQh[row * QSTR + kc * 16 + colb]));
            ldsm_x4(qa_l[kc][0], qa_l[kc][1], qa_l[kc][2], qa_l[kc][3],
                    s2u(&sQl[row * QSTR + kc * 16 + colb]));
        }
    }

    const __half* Khp = g_Kh + (size_t)h * SEQ * HD;
    const __half* Klp = g_Kl + (size_t)h * SEQ * HD;
    const __half* Vhp = g_Vh + (size_t)h * SEQ * HD;
    const __half* Vlp = g_Vl + (size_t)h * SEQ * HD;

    int q0 = qb + qg * 16 + g;
    float inv0 = g_inv[h * SEQ + q0];
    float inv1 = g_inv[h * SEQ + q0 + 8];
    const u32* mwp0 = g_mbits + (size_t)q0 * MW + kg;  // word 2t + kg
    const u32* mwp1 = mwp0 + (size_t)8 * MW;
    float* abase = attn_out + ((size_t)h * SEQ + qb) * SEQ;

    float oc[4][4] = {};
    int ldr = tid >> 2, ldc = tid & 3;  // KV loads: 64 rows x 4 chunks

#define ISSUE_TILE(stage, kc0)                                                            \
    {                                                                                     \
        char* kv = sKV0 + (stage)*KVBYTES;                                                \
        size_t goff = (size_t)((kc0) + ldr) * HD + ldc * 8;                               \
        u32 so = (u32)(ldr * QSTR + ldc * 8) * 2;                                         \
        cp16(s2u(kv) + so, Khp + goff);                                                   \
        cp16(s2u(kv + 64 * QSTR * 2) + so, Klp + goff);                                   \
        cp16(s2u(kv + 2 * 64 * QSTR * 2) + so, Vhp + goff);                               \
        cp16(s2u(kv + 3 * 64 * QSTR * 2) + so, Vlp + goff);                               \
        cp_commit();                                                                      \
    }

    ISSUE_TILE(0, 0);
    for (int t = 0; t < 64; t++) {
        cp_wait<0>();          // tile t landed
        __syncthreads();       // all threads see KV t; prior Es copy done
        if (t + 1 < 64) ISSUE_TILE((t + 1) & 1, (t + 1) * 64);
        char* kv = sKV0 + (t & 1) * KVBYTES;
        const __half* sKh = (const __half*)kv;
        const __half* sKl = sKh + 64 * QSTR;
        const __half* sVh = sKl + 64 * QSTR;
        const __half* sVl = sVh + 64 * QSTR;
        int kc0 = t * 64;

        u32 m0 = mwp0[t * 2] >> (tig * 2);
        u32 m1 = mwp1[t * 2] >> (tig * 2);

        u32 eh[2][4];
#pragma unroll
        for (int j = 0; j < 4; j++) {
            u32 bh[4], bl[4];
            u32 base = (kg * 32 + j * 8 + (lane & 7)) * QSTR + ((lane >> 3) & 3) * 8;
            ldsm_x4(bh[0], bh[1], bh[2], bh[3], s2u(sKh + base));
            ldsm_x4(bl[0], bl[1], bl[2], bl[3], s2u(sKl + base));
            float c[4] = {0, 0, 0, 0};
            mma_f16(c, qa_h[0], bh[0], bh[1]);
            mma_f16(c, qa_h[1], bh[2], bh[3]);
            mma_f16(c, qa_h[0], bl[0], bl[1]);
            mma_f16(c, qa_h[1], bl[2], bl[3]);
            mma_f16(c, qa_l[0], bh[0], bh[1]);
            mma_f16(c, qa_l[1], bh[2], bh[3]);
            u32 b0 = m0 >> (j * 8), b1 = m1 >> (j * 8);
            float e0 = (b0 & 1) ? 0.0f : ex2(c[0]) * inv0;
            float e1 = (b0 & 2) ? 0.0f : ex2(c[1]) * inv0;
            float e2 = (b1 & 1) ? 0.0f : ex2(c[2]) * inv1;
            float e3 = (b1 & 2) ? 0.0f : ex2(c[3]) * inv1;
            int kk = kg * 32 + j * 8 + tig * 2;
            int r0 = qg * 16 + g;
            *(float2*)(sEs + r0 * ESTR + kk) = make_float2(e0, e1);
            *(float2*)(sEs + (r0 + 8) * ESTR + kk) = make_float2(e2, e3);
            int kc2 = j >> 1, off = (j & 1) * 2;
            eh[kc2][off + 0] = hpack(e0, e1);
            eh[kc2][off + 1] = hpack(e2, e3);
        }
        // context partials over this warp's 32 keys: ctx += Ehi*Vhi + Ehi*Vlo
#pragma unroll
        for (int jd = 0; jd < 4; jd++) {
            u32 vh[4], vl[4];
            ldsm_x4t(vh[0], vh[1], vh[2], vh[3], s2u(sVh + (kg * 32 + lane) * QSTR + jd * 8));
            ldsm_x4t(vl[0], vl[1], vl[2], vl[3], s2u(sVl + (kg * 32 + lane) * QSTR + jd * 8));
#pragma unroll
            for (int kc2 = 0; kc2 < 2; kc2++) {
                mma_f16(oc[jd], eh[kc2], vh[kc2 * 2], vh[kc2 * 2 + 1]);
                mma_f16(oc[jd], eh[kc2], vl[kc2 * 2], vl[kc2 * 2 + 1]);
            }
        }
        __syncthreads();  // Es complete from all warps
        // coalesced copy: 64 rows x 64 floats -> gmem (float4, full 256B rows)
        for (int i = tid; i < 64 * 16; i += 256) {
            int row = i >> 4, c4 = i & 15;
            *((float4*)(abase + (size_t)row * SEQ + kc0) + c4) =
                *(const float4*)(sEs + row * ESTR + c4 * 4);
        }
    }
#undef ISSUE_TILE

    // ---- cross-warp (kg) context reduce via smem, then write g_ctx ----
    __syncthreads();
    float* sc = (float*)sKV0;  // [2][64][33] floats = 16896 B, fits in KV region
    {
        int r = qg * 16 + g;
#pragma unroll
        for (int jd = 0; jd < 4; jd++) {
            float* p0 = sc + (kg * 64 + r) * 33 + jd * 8 + tig * 2;
            p0[0] = oc[jd][0];
            p0[1] = oc[jd][1];
            float* p1 = sc + (kg * 64 + r + 8) * 33 + jd * 8 + tig * 2;
            p1[0] = oc[jd][2];
            p1[1] = oc[jd][3];
        }
    }
    __syncthreads();
    for (int i = tid; i < 64 * 32; i += 256) {
        int row = i >> 5, col = i & 31;
        g_ctx[(size_t)(qb + row) * DM + h * HD + col] =
            sc[row * 33 + col] + sc[(64 + row) * 33 + col];
    }
}

// ---------------- output projection: g_fc = ctx @ W_fc^T ----------------
__global__ __launch_bounds__(256) void fc_kernel(const float* __restrict__ W) {
    __shared__ float Xs[16][68];
    __shared__ float Ws[16][68];
    int bm = blockIdx.y * 64, bn = blockIdx.x * 64;
    int tid = threadIdx.x;
    int tx = (tid & 15) * 4, ty = (tid >> 4) * 4;
    float acc[4][4] = {};
    for (int k0 = 0; k0 < DM; k0 += 16) {
        for (int i = tid; i < 1024; i += 256) {
            int r = i >> 4, kk = i & 15;
            int c = k0 + kk;
            Xs[kk][r] = g_ctx[(size_t)(bm + r) * DM + c];
            Ws[kk][r] = W[(size_t)(bn + r) * DM + c];
        }
        __syncthreads();
#pragma unroll
        for (int kk = 0; kk < 16; kk++) {
            float xv[4], wv[4];
#pragma unroll
            for (int i = 0; i < 4; i++) xv[i] = Xs[kk][ty + i];
#pragma unroll
            for (int j = 0; j < 4; j++) wv[j] = Ws[kk][tx + j];
#pragma unroll
            for (int i = 0; i < 4; i++)
#pragma unroll
                for (int j = 0; j < 4; j++) acc[i][j] += xv[i] * wv[j];
        }
        __syncthreads();
    }
#pragma unroll
    for (int i = 0; i < 4; i++)
#pragma unroll
        for (int j = 0; j < 4; j++)
            g_fc[(size_t)(bm + ty + i) * DM + bn + tx + j] = acc[i][j];
}

// ---------------- LayerNorm ----------------
__global__ __launch_bounds__(256) void ln_kernel(const float* __restrict__ lnw,
                                                 const float* __restrict__ lnb,
                                                 float* __restrict__ out) {
    int n = blockIdx.x, t = threadIdx.x, lane = t & 31, w = t >> 5;
    __shared__ float red[8];
    float x = g_fc[(size_t)n * DM + t];
    float s = x;
#pragma unroll
    for (int o = 16; o; o >>= 1) s += __shfl_xor_sync(0xFFFFFFFFu, s, o);
    if (lane == 0) red[w] = s;
    __syncthreads();
    float mu = 0;
#pragma unroll
    for (int i = 0; i < 8; i++) mu += red[i];
    mu *= (1.0f / DM);
    __syncthreads();
    float d = x - mu;
    float s2 = d * d;
#pragma unroll
    for (int o = 16; o; o >>= 1) s2 += __shfl_xor_sync(0xFFFFFFFFu, s2, o);
    if (lane == 0) red[w] = s2;
    __syncthreads();
    float var = 0;
#pragma unroll
    for (int i = 0; i < 8; i++) var += red[i];
    var *= (1.0f / DM);
    out[(size_t)n * DM + t] = d * rsqrtf(var + 1e-5f) * lnw[t] + lnb[t];
}

// ---------------- launch ----------------
extern "C" void kernel_launch(void* const* d_in, const int* in_sizes, int n_in,
                              void* d_out, int out_size) {
    const float* iQ = (const float*)d_in[0];
    const float* iK = (const float*)d_in[1];
    const float* iV = (const float*)d_in[2];
    const void* mask = d_in[3];
    const float* WQ = (const float*)d_in[4];
    const float* WK = (const float*)d_in[5];
    const float* WV = (const float*)d_in[6];
    const float* Wfc = (const float*)d_in[7];
    const float* lnw = (const float*)d_in[8];
    const float* lnb = (const float*)d_in[9];
    float* out = (float*)d_out;

    long long attn_elems = (long long)NH * SEQ * SEQ;
    long long attn_off = (long long)out_size - attn_elems;
    float* attn_out = (attn_off >= 0) ? (out + attn_off) : out;

    cudaFuncSetAttribute(attn_kernel, cudaFuncAttributeMaxDynamicSharedMemorySize, ATTN_SMEM);

    detect_mask_kernel<<<1, 32>>>(mask);
    conv_mask_kernel<<<4096, 256>>>(mask);
    proj_kernel<<<dim3(4, 64, 3), 256>>>(iQ, iK, iV, WQ, WK, WV);
    rowsum_kernel<<<dim3(128, 8), 256>>>();
    attn_kernel<<<dim3(64, 8), 256, ATTN_SMEM>>>(attn_out);
    fc_kernel<<<dim3(4, 64), 256>>>(Wfc);
    ln_kernel<<<SEQ, 256>>>(lnw, lnb, out);
}

// round 16
// speedup vs baseline: 1.2035x; 1.2035x over previous
#include <cuda_runtime.h>
#include <cuda_fp16.h>
#include <math.h>

#define SEQ 4096
#define NH 8
#define HD 32
#define DM 256
#define IN_F 256
#define MW (SEQ / 32)  // mask words per row

typedef unsigned int u32;

// ---------------- scratch (static device globals; no allocation) ----------------
__device__ __align__(16) __half g_Qh[NH * SEQ * HD];  // fp16 hi, Q pre-scaled by log2e/sqrt(32)
__device__ __align__(16) __half g_Ql[NH * SEQ * HD];  // fp16 residual
__device__ __align__(16) __half g_Kh[NH * SEQ * HD];
__device__ __align__(16) __half g_Kl[NH * SEQ * HD];
__device__ __align__(16) __half g_Vh[NH * SEQ * HD];
__device__ __align__(16) __half g_Vl[NH * SEQ * HD];
__device__ float g_inv[NH * SEQ];              // 1 / softmax rowsum
__device__ float g_ctx[SEQ * DM];              // normalized context
__device__ float g_fc[SEQ * DM];
__device__ u32 g_mbits[(size_t)SEQ * MW];      // bit-packed mask (bit=1 => masked), 2MB
__device__ int g_mask_mode;

// ---------------- small helpers ----------------
__device__ __forceinline__ u32 s2u(const void* p) { return (u32)__cvta_generic_to_shared(p); }

__device__ __forceinline__ void cp16(u32 dst, const void* src) {
    asm volatile("cp.async.cg.shared.global [%0], [%1], 16;" :: "r"(dst), "l"(src));
}
__device__ __forceinline__ void cp_commit() { asm volatile("cp.async.commit_group;"); }
template <int N>
__device__ __forceinline__ void cp_wait() { asm volatile("cp.async.wait_group %0;" :: "n"(N)); }

__device__ __forceinline__ void ldsm_x4(u32& r0, u32& r1, u32& r2, u32& r3, u32 addr) {
    asm volatile("ldmatrix.sync.aligned.m8n8.x4.shared.b16 {%0,%1,%2,%3}, [%4];"
                 : "=r"(r0), "=r"(r1), "=r"(r2), "=r"(r3) : "r"(addr));
}
__device__ __forceinline__ void ldsm_x4t(u32& r0, u32& r1, u32& r2, u32& r3, u32 addr) {
    asm volatile("ldmatrix.sync.aligned.m8n8.x4.trans.shared.b16 {%0,%1,%2,%3}, [%4];"
                 : "=r"(r0), "=r"(r1), "=r"(r2), "=r"(r3) : "r"(addr));
}
__device__ __forceinline__ void mma_f16(float* c, const u32* a, u32 b0, u32 b1) {
    asm volatile(
        "mma.sync.aligned.m16n8k16.row.col.f32.f16.f16.f32 "
        "{%0,%1,%2,%3}, {%4,%5,%6,%7}, {%8,%9}, {%0,%1,%2,%3};"
        : "+f"(c[0]), "+f"(c[1]), "+f"(c[2]), "+f"(c[3])
        : "r"(a[0]), "r"(a[1]), "r"(a[2]), "r"(a[3]), "r"(b0), "r"(b1));
}
__device__ __forceinline__ u32 hpack(float lo, float hi) {
    u32 r;
    asm("cvt.rn.f16x2.f32 %0, %1, %2;" : "=r"(r) : "f"(hi), "f"(lo));
    return r;
}
// scores are pre-scaled by log2e: exp(s) == ex2(c), single MUFU op
__device__ __forceinline__ float ex2(float x) {
    float r;
    asm("ex2.approx.f32 %0, %1;" : "=f"(r) : "f"(x));
    return r;
}

// ---------------- mask dtype detection + bit-pack canonicalization ----------------
__global__ void detect_mask_kernel(const void* m) {
    const unsigned int* p = (const unsigned int*)m;
    int lane = threadIdx.x;
    int isint = 1, isfloat = 1;
    for (int i = lane; i < 256; i += 32) {
        unsigned int v = p[i];
        if (v > 1u) isint = 0;
        if (v != 0u && v != 0x3F800000u) isfloat = 0;
    }
    isint = __all_sync(0xFFFFFFFFu, isint);
    isfloat = __all_sync(0xFFFFFFFFu, isfloat);
    if (lane == 0) g_mask_mode = isint ? 1 : (isfloat ? 2 : 0);
}

__global__ void conv_mask_kernel(const void* m) {
    int mode = g_mask_mode;
    int lane = threadIdx.x & 31;
    size_t idx = (size_t)blockIdx.x * blockDim.x + threadIdx.x;
    size_t stride = (size_t)gridDim.x * blockDim.x;
    size_t total = (size_t)SEQ * SEQ;
    for (size_t i = idx; i < total; i += stride) {
        int pred;
        if (mode == 1)      pred = (((const int*)m)[i] != 0);
        else if (mode == 2) pred = (((const float*)m)[i] != 0.0f);
        else                pred = (((const unsigned char*)m)[i] != 0);
        u32 b = __ballot_sync(0xFFFFFFFFu, pred);
        if (lane == 0) g_mbits[i >> 5] = b;
    }
}

// ---------------- input projections: Y = X @ W^T -> fp16 hi/lo, split heads ----------------
__global__ __launch_bounds__(256) void proj_kernel(const float* __restrict__ XQ,
                                                   const float* __restrict__ XK,
                                                   const float* __restrict__ XV,
                                                   const float* __restrict__ WQ,
                                                   const float* __restrict__ WK,
                                                   const float* __restrict__ WV) {
    int which = blockIdx.z;
    const float* X = (which == 0) ? XQ : (which == 1) ? XK : XV;
    const float* W = (which == 0) ? WQ : (which == 1) ? WK : WV;
    __half* oh = (which == 0) ? g_Qh : (which == 1) ? g_Kh : g_Vh;
    __half* ol = (which == 0) ? g_Ql : (which == 1) ? g_Kl : g_Vl;
    // Q carries 1/sqrt(32) * log2(e) so softmax exp becomes a bare ex2
    float scale = (which == 0) ? (0.17677669529663687f * 1.4426950408889634f) : 1.0f;
    __shared__ float Xs[16][68];
    __shared__ float Ws[16][68];
    int bm = blockIdx.y * 64, bn = blockIdx.x * 64;
    int tid = threadIdx.x;
    int tx = (tid & 15) * 4, ty = (tid >> 4) * 4;
    float acc[4][4] = {};
    for (int k0 = 0; k0 < IN_F; k0 += 16) {
        for (int i = tid; i < 1024; i += 256) {
            int r = i >> 4, kk = i & 15;
            Xs[kk][r] = X[(size_t)(bm + r) * IN_F + k0 + kk];
            Ws[kk][r] = W[(size_t)(bn + r) * IN_F + k0 + kk];
        }
        __syncthreads();
#pragma unroll
        for (int kk = 0; kk < 16; kk++) {
            float xv[4], wv[4];
#pragma unroll
            for (int i = 0; i < 4; i++) xv[i] = Xs[kk][ty + i];
#pragma unroll
            for (int j = 0; j < 4; j++) wv[j] = Ws[kk][tx + j];
#pragma unroll
            for (int i = 0; i < 4; i++)
#pragma unroll
                for (int j = 0; j < 4; j++) acc[i][j] += xv[i] * wv[j];
        }
        __syncthreads();
    }
#pragma unroll
    for (int i = 0; i < 4; i++) {
        int m = bm + ty + i;
#pragma unroll
        for (int j = 0; j < 4; j++) {
            int o = bn + tx + j;
            float v = acc[i][j] * scale;
            __half hi = __float2half_rn(v);
            float lo = v - __half2float(hi);
            size_t dst = (size_t)(o >> 5) * (SEQ * HD) + (size_t)m * HD + (o & 31);
            oh[dst] = hi;
            ol[dst] = __float2half_rn(lo);
        }
    }
}

#define QSTR 40  // half row stride for Q/K/V smem tiles (80B: 16B-aligned, ldsm conflict-free)

// ================= rowsum kernel: g_inv = 1/sum(exp(scores)) =================
// q-tile 32 (grid 1024). 128-key iterations (halved syncs/loop overhead), 3 stages.
// Warp (qg = w&1, kg = w>>1) owns q rows [qg*16,+16) x keys [kg*16,+16) of each 64-key block.
__global__ __launch_bounds__(256, 5) void rowsum_kernel() {
    __shared__ __align__(16) __half sQ[32 * QSTR];
    __shared__ __align__(16) __half sK[3][128 * QSTR];
    __shared__ float sred[32][5];

    int h = blockIdx.y;
    int qb = blockIdx.x * 32;
    int tid = threadIdx.x, w = tid >> 5, lane = tid & 31;
    int g = lane >> 2, tig = lane & 3;
    int qg = w & 1, kg = w >> 1;

    // stage Q hi (32 rows x 4 chunks)
    if (tid < 128) {
        int r = tid >> 2, c = tid & 3;
        *(uint4*)(sQ + r * QSTR + c * 8) =
            *(const uint4*)(g_Qh + ((size_t)h * SEQ + qb + r) * HD + c * 8);
    }
    __syncthreads();

    // A-fragments: 1 row group of 16 (hi only) = 8 regs
    u32 qa[2][4];
    {
        int colb = ((lane >> 4) & 1) * 8;
        int row = qg * 16 + (lane & 15);
#pragma unroll
        for (int kc = 0; kc < 2; kc++)
            ldsm_x4(qa[kc][0], qa[kc][1], qa[kc][2], qa[kc][3],
                    s2u(&sQ[row * QSTR + kc * 16 + colb]));
    }

    const __half* Khp = g_Kh + (size_t)h * SEQ * HD;
    int ldr = tid >> 2, ldc = tid & 3;  // rows ldr and ldr+64, chunk ldc
    float rs0 = 0.0f, rs1 = 0.0f;

    int q0 = qb + qg * 16 + g;
    const u32* mwp0 = g_mbits + (size_t)q0 * MW + (kg >> 1);
    const u32* mwp1 = mwp0 + (size_t)8 * MW;
    int bitbase = (kg & 1) * 16 + tig * 2;

#define RS_ISSUE(stage, kc0)                                                       \
    {                                                                              \
        cp16(s2u(sK[(stage)] + ldr * QSTR + ldc * 8),                              \
             Khp + (size_t)((kc0) + ldr) * HD + ldc * 8);                          \
        cp16(s2u(sK[(stage)] + (ldr + 64) * QSTR + ldc * 8),                       \
             Khp + (size_t)((kc0) + ldr + 64) * HD + ldc * 8);                     \
        cp_commit();                                                               \
    }

    RS_ISSUE(0, 0);
    RS_ISSUE(1, 128);
    for (int T = 0; T < 32; T++) {
        if (T < 31) cp_wait<1>(); else cp_wait<0>();
        __syncthreads();
        if (T + 2 < 32) RS_ISSUE((T + 2) % 3, (T + 2) * 128);
        const __half* sKb = sK[T % 3];
        // mask words: 64-key blocks 2T and 2T+1 -> row words T*4 and T*4+2 (+ (kg>>1) in ptr)
        u32 mw0[2], mw1[2];
        mw0[0] = mwp0[T * 4] >> bitbase;
        mw0[1] = mwp0[T * 4 + 2] >> bitbase;
        mw1[0] = mwp1[T * 4] >> bitbase;
        mw1[1] = mwp1[T * 4 + 2] >> bitbase;
#pragma unroll
        for (int b = 0; b < 2; b++) {
#pragma unroll
            for (int j = 0; j < 2; j++) {
                u32 bh[4];
                ldsm_x4(bh[0], bh[1], bh[2], bh[3],
                        s2u(sKb + (b * 64 + kg * 16 + j * 8 + (lane & 7)) * QSTR +
                            ((lane >> 3) & 3) * 8));
                float c[4] = {0, 0, 0, 0};
                mma_f16(c, qa[0], bh[0], bh[1]);
                mma_f16(c, qa[1], bh[2], bh[3]);
                u32 b0 = mw0[b] >> (j * 8), b1 = mw1[b] >> (j * 8);
                rs0 += ((b0 & 1) ? 0.0f : ex2(c[0])) + ((b0 & 2) ? 0.0f : ex2(c[1]));
                rs1 += ((b1 & 1) ? 0.0f : ex2(c[2])) + ((b1 & 2) ? 0.0f : ex2(c[3]));
            }
        }
    }
#undef RS_ISSUE

    rs0 += __shfl_xor_sync(0xFFFFFFFFu, rs0, 1);
    rs0 += __shfl_xor_sync(0xFFFFFFFFu, rs0, 2);
    rs1 += __shfl_xor_sync(0xFFFFFFFFu, rs1, 1);
    rs1 += __shfl_xor_sync(0xFFFFFFFFu, rs1, 2);
    if (tig == 0) {
        int r = qg * 16 + g;
        sred[r][kg] = rs0;
        sred[r + 8][kg] = rs1;
    }
    __syncthreads();
    if (tid < 32)
        g_inv[h * SEQ + qb + tid] =
            1.0f / (sred[tid][0] + sred[tid][1] + sred[tid][2] + sred[tid][3]);
}

// ================= attention kernel: normalized attn + context (single pass) =================
// R13-proven structure: q-tile 128, 3-stage 64-key KV pipeline, direct register stores.
#define KVBYTES (4 * 64 * QSTR * 2)                          // 20480 per stage
#define ATTN_SMEM (2 * 128 * QSTR * 2 + 3 * KVBYTES)         // 81920

__global__ __launch_bounds__(256, 2) void attn_kernel(float* __restrict__ attn_out) {
    extern __shared__ char smem_raw[];
    __half* sQh = (__half*)smem_raw;
    __half* sQl = sQh + 128 * QSTR;
    char* sKV0 = smem_raw + 2 * 128 * QSTR * 2;

    int h = blockIdx.y;
    int qb = blockIdx.x * 128;
    int tid = threadIdx.x, w = tid >> 5, lane = tid & 31;
    int g = lane >> 2, tig = lane & 3;
    int qg = w & 3, kg = w >> 2;

    // stage Q hi/lo
    for (int i = tid; i < 128 * 4; i += 256) {
        int r = i >> 2, c = i & 3;
        *(uint4*)(sQh + r * QSTR + c * 8) =
            *(const uint4*)(g_Qh + ((size_t)h * SEQ + qb + r) * HD + c * 8);
        *(uint4*)(sQl + r * QSTR + c * 8) =
            *(const uint4*)(g_Ql + ((size_t)h * SEQ + qb + r) * HD + c * 8);
    }
    __syncthreads();

    u32 qa_h[2][2][4], qa_l[2][2][4];
    {
        int colb = ((lane >> 4) & 1) * 8;
#pragma unroll
        for (int rg = 0; rg < 2; rg++) {
            int row = qg * 32 + rg * 16 + (lane & 15);
#pragma unroll
            for (int kc = 0; kc < 2; kc++) {
                ldsm_x4(qa_h[rg][kc][0], qa_h[rg][kc][1], qa_h[rg][kc][2], qa_h[rg][kc][3],
                        s2u(&sQh[row * QSTR + kc * 16 + colb]));
                ldsm_x4(qa_l[rg][kc][0], qa_l[rg][kc][1], qa_l[rg][kc][2], qa_l[rg][kc][3],
                        s2u(&sQl[row * QSTR + kc * 16 + colb]));
            }
        }
    }

    const __half* Khp = g_Kh + (size_t)h * SEQ * HD;
    const __half* Klp = g_Kl + (size_t)h * SEQ * HD;
    const __half* Vhp = g_Vh + (size_t)h * SEQ * HD;
    const __half* Vlp = g_Vl + (size_t)h * SEQ * HD;

    float inv[2][2];
    float* ar[2][2];
    const u32* mw0[2];
    const u32* mw1[2];
#pragma unroll
    for (int rg = 0; rg < 2; rg++) {
        int q = qb + qg * 32 + rg * 16 + g;
        inv[rg][0] = g_inv[h * SEQ + q];
        inv[rg][1] = g_inv[h * SEQ + q + 8];
        ar[rg][0] = attn_out + ((size_t)h * SEQ + q) * SEQ;
        ar[rg][1] = ar[rg][0] + (size_t)8 * SEQ;
        mw0[rg] = g_mbits + (size_t)q * MW + kg;   // word 2t + kg
        mw1[rg] = mw0[rg] + (size_t)8 * MW;
    }

    float oc[2][4][4] = {};
    int ldr = tid >> 2, ldc = tid & 3;  // KV loads: 64 rows x 4 chunks

#define ISSUE_TILE(stage, kc0)                                                            \
    {                                                                                     \
        char* kv = sKV0 + (stage)*KVBYTES;                                                \
        size_t goff = (size_t)((kc0) + ldr) * HD + ldc * 8;                               \
        u32 so = (u32)(ldr * QSTR + ldc * 8) * 2;                                         \
        cp16(s2u(kv) + so, Khp + goff);                                                   \
        cp16(s2u(kv + 64 * QSTR * 2) + so, Klp + goff);                                   \
        cp16(s2u(kv + 2 * 64 * QSTR * 2) + so, Vhp + goff);                               \
        cp16(s2u(kv + 3 * 64 * QSTR * 2) + so, Vlp + goff);                               \
        cp_commit();                                                                      \
    }

    ISSUE_TILE(0, 0);
    ISSUE_TILE(1, 64);
    for (int t = 0; t < 64; t++) {
        if (t < 63) cp_wait<1>(); else cp_wait<0>();
        __syncthreads();
        if (t + 2 < 64) ISSUE_TILE((t + 2) % 3, (t + 2) * 64);
        char* kv = sKV0 + (t % 3) * KVBYTES;
        const __half* sKh = (const __half*)kv;
        const __half* sKl = sKh + 64 * QSTR;
        const __half* sVh = sKl + 64 * QSTR;
        const __half* sVl = sVh + 64 * QSTR;
        int kc0 = t * 64;

        // mask words for this tile (L2-resident bitmask)
        u32 m0[2], m1[2];
#pragma unroll
        for (int rg = 0; rg < 2; rg++) {
            m0[rg] = mw0[rg][t * 2] >> (tig * 2);
            m1[rg] = mw1[rg][t * 2] >> (tig * 2);
        }

        u32 eh[2][2][4];
#pragma unroll
        for (int j = 0; j < 4; j++) {
            u32 bh[4], bl[4];
            u32 base = (kg * 32 + j * 8 + (lane & 7)) * QSTR + ((lane >> 3) & 3) * 8;
            ldsm_x4(bh[0], bh[1], bh[2], bh[3], s2u(sKh + base));
            ldsm_x4(bl[0], bl[1], bl[2], bl[3], s2u(sKl + base));
            int kk = kg * 32 + j * 8 + tig * 2;
            int kc2 = j >> 1, off = (j & 1) * 2;
#pragma unroll
            for (int rg = 0; rg < 2; rg++) {
                float c[4] = {0, 0, 0, 0};
                mma_f16(c, qa_h[rg][0], bh[0], bh[1]);
                mma_f16(c, qa_h[rg][1], bh[2], bh[3]);
                mma_f16(c, qa_h[rg][0], bl[0], bl[1]);
                mma_f16(c, qa_h[rg][1], bl[2], bl[3]);
                mma_f16(c, qa_l[rg][0], bh[0], bh[1]);
                mma_f16(c, qa_l[rg][1], bh[2], bh[3]);
                u32 b0 = m0[rg] >> (j * 8), b1 = m1[rg] >> (j * 8);
                float e0 = (b0 & 1) ? 0.0f : ex2(c[0]) * inv[rg][0];
                float e1 = (b0 & 2) ? 0.0f : ex2(c[1]) * inv[rg][0];
                float e2 = (b1 & 1) ? 0.0f : ex2(c[2]) * inv[rg][1];
                float e3 = (b1 & 2) ? 0.0f : ex2(c[3]) * inv[rg][1];
                *(float2*)(ar[rg][0] + kc0 + kk) = make_float2(e0, e1);
                *(float2*)(ar[rg][1] + kc0 + kk) = make_float2(e2, e3);
                // E as fp16 A-fragment (hi only)
                eh[rg][kc2][off + 0] = hpack(e0, e1);
                eh[rg][kc2][off + 1] = hpack(e2, e3);
            }
        }
        // context partials over this warp's 32 keys: ctx += Ehi*Vhi + Ehi*Vlo
#pragma unroll
        for (int jd = 0; jd < 4; jd++) {
            u32 vh[4], vl[4];
            ldsm_x4t(vh[0], vh[1], vh[2], vh[3], s2u(sVh + (kg * 32 + lane) * QSTR + jd * 8));
            ldsm_x4t(vl[0], vl[1], vl[2], vl[3], s2u(sVl + (kg * 32 + lane) * QSTR + jd * 8));
#pragma unroll
            for (int rg = 0; rg < 2; rg++)
#pragma unroll
                for (int kc2 = 0; kc2 < 2; kc2++) {
                    mma_f16(oc[rg][jd], eh[rg][kc2], vh[kc2 * 2], vh[kc2 * 2 + 1]);
                    mma_f16(oc[rg][jd], eh[rg][kc2], vl[kc2 * 2], vl[kc2 * 2 + 1]);
                }
        }
    }
#undef ISSUE_TILE

    // ---- cross-warp (kg) context reduce via smem, then write g_ctx ----
    __syncthreads();
    float* sc = (float*)sKV0;  // [2][128][33] floats = 33792 B, fits in KV region
#pragma unroll
    for (int rg = 0; rg < 2; rg++) {
        int r = qg * 32 + rg * 16 + g;
#pragma unroll
        for (int jd = 0; jd < 4; jd++) {
            float* p0 = sc + (kg * 128 + r) * 33 + jd * 8 + tig * 2;
            p0[0] = oc[rg][jd][0];
            p0[1] = oc[rg][jd][1];
            float* p1 = sc + (kg * 128 + r + 8) * 33 + jd * 8 + tig * 2;
            p1[0] = oc[rg][jd][2];
            p1[1] = oc[rg][jd][3];
        }
    }
    __syncthreads();
    for (int i = tid; i < 128 * 32; i += 256) {
        int row = i >> 5, col = i & 31;
        g_ctx[(size_t)(qb + row) * DM + h * HD + col] =
            sc[row * 33 + col] + sc[(128 + row) * 33 + col];
    }
}

// ---------------- output projection: g_fc = ctx @ W_fc^T ----------------
__global__ __launch_bounds__(256) void fc_kernel(const float* __restrict__ W) {
    __shared__ float Xs[16][68];
    __shared__ float Ws[16][68];
    int bm = blockIdx.y * 64, bn = blockIdx.x * 64;
    int tid = threadIdx.x;
    int tx = (tid & 15) * 4, ty = (tid >> 4) * 4;
    float acc[4][4] = {};
    for (int k0 = 0; k0 < DM; k0 += 16) {
        for (int i = tid; i < 1024; i += 256) {
            int r = i >> 4, kk = i & 15;
            int c = k0 + kk;
            Xs[kk][r] = g_ctx[(size_t)(bm + r) * DM + c];
            Ws[kk][r] = W[(size_t)(bn + r) * DM + c];
        }
        __syncthreads();
#pragma unroll
        for (int kk = 0; kk < 16; kk++) {
            float xv[4], wv[4];
#pragma unroll
            for (int i = 0; i < 4; i++) xv[i] = Xs[kk][ty + i];
#pragma unroll
            for (int j = 0; j < 4; j++) wv[j] = Ws[kk][tx + j];
#pragma unroll
            for (int i = 0; i < 4; i++)
#pragma unroll
                for (int j = 0; j < 4; j++) acc[i][j] += xv[i] * wv[j];
        }
        __syncthreads();
    }
#pragma unroll
    for (int i = 0; i < 4; i++)
#pragma unroll
        for (int j = 0; j < 4; j++)
            g_fc[(size_t)(bm + ty + i) * DM + bn + tx + j] = acc[i][j];
}

// ---------------- LayerNorm ----------------
__global__ __launch_bounds__(256) void ln_kernel(const float* __restrict__ lnw,
                                                 const float* __restrict__ lnb,
                                                 float* __restrict__ out) {
    int n = blockIdx.x, t = threadIdx.x, lane = t & 31, w = t >> 5;
    __shared__ float red[8];
    float x = g_fc[(size_t)n * DM + t];
    float s = x;
#pragma unroll
    for (int o = 16; o; o >>= 1) s += __shfl_xor_sync(0xFFFFFFFFu, s, o);
    if (lane == 0) red[w] = s;
    __syncthreads();
    float mu = 0;
#pragma unroll
    for (int i = 0; i < 8; i++) mu += red[i];
    mu *= (1.0f / DM);
    __syncthreads();
    float d = x - mu;
    float s2 = d * d;
#pragma unroll
    for (int o = 16; o; o >>= 1) s2 += __shfl_xor_sync(0xFFFFFFFFu, s2, o);
    if (lane == 0) red[w] = s2;
    __syncthreads();
    float var = 0;
#pragma unroll
    for (int i = 0; i < 8; i++) var += red[i];
    var *= (1.0f / DM);
    out[(size_t)n * DM + t] = d * rsqrtf(var + 1e-5f) * lnw[t] + lnb[t];
}

// ---------------- launch ----------------
extern "C" void kernel_launch(void* const* d_in, const int* in_sizes, int n_in,
                              void* d_out, int out_size) {
    const float* iQ = (const float*)d_in[0];
    const float* iK = (const float*)d_in[1];
    const float* iV = (const float*)d_in[2];
    const void* mask = d_in[3];
    const float* WQ = (const float*)d_in[4];
    const float* WK = (const float*)d_in[5];
    const float* WV = (const float*)d_in[6];
    const float* Wfc = (const float*)d_in[7];
    const float* lnw = (const float*)d_in[8];
    const float* lnb = (const float*)d_in[9];
    float* out = (float*)d_out;

    long long attn_elems = (long long)NH * SEQ * SEQ;
    long long attn_off = (long long)out_size - attn_elems;
    float* attn_out = (attn_off >= 0) ? (out + attn_off) : out;

    cudaFuncSetAttribute(attn_kernel, cudaFuncAttributeMaxDynamicSharedMemorySize, ATTN_SMEM);

    detect_mask_kernel<<<1, 32>>>(mask);
    conv_mask_kernel<<<4096, 256>>>(mask);
    proj_kernel<<<dim3(4, 64, 3), 256>>>(iQ, iK, iV, WQ, WK, WV);
    rowsum_kernel<<<dim3(128, 8), 256>>>();
    attn_kernel<<<dim3(32, 8), 256, ATTN_SMEM>>>(attn_out);
    fc_kernel<<<dim3(4, 64), 256>>>(Wfc);
    ln_kernel<<<SEQ, 256>>>(lnw, lnb, out);
}